// round 4
// baseline (speedup 1.0000x reference)
#include <cuda_runtime.h>

#define LSEQ 768
#define NSEQ 256
#define MD   256
#define MSAD 23
#define SEQD 22
#define ZD   128
#define NB   14
#define RC   32
#define RSTRIDE 260   // floats per k-row in duplicated smem (256 + pad, mult of 4)

// Scratch: kb[i,:] = seq@Wk + bk + bpos  (384 KB)
__device__ float g_kb[LSEQ * ZD];

// ---- packed f32x2 helpers (sm_103a, PTX-only) ----
typedef unsigned long long ull;
__device__ __forceinline__ ull pk2(float a, float b) {
    ull r; asm("mov.b64 %0, {%1, %2};" : "=l"(r) : "f"(a), "f"(b)); return r;
}
__device__ __forceinline__ ull fma2(ull a, ull b, ull c) {
    ull d; asm("fma.rn.f32x2 %0, %1, %2, %3;" : "=l"(d) : "l"(a), "l"(b), "l"(c));
    return d;
}
__device__ __forceinline__ ull add2(ull a, ull b) {
    ull d; asm("add.rn.f32x2 %0, %1, %2;" : "=l"(d) : "l"(a), "l"(b)); return d;
}
__device__ __forceinline__ void st2cs(float* p, ull a, ull b) {
    asm volatile("st.global.cs.v2.u64 [%0], {%1, %2};" :: "l"(p), "l"(a), "l"(b) : "memory");
}
__device__ __forceinline__ float4 ld4(const float* p) {
    return *reinterpret_cast<const float4*>(p);
}

// ---------------------------------------------------------------------------
// kb precompute: 2 rows per 256-thread block.
// ---------------------------------------------------------------------------
__global__ __launch_bounds__(256) void kbkern(
    const float* __restrict__ seq, const float* __restrict__ Wk,
    const float* __restrict__ bk,  const float* __restrict__ bpos)
{
    const int tid = threadIdx.x;
    const int rr  = tid >> 7;
    const int c   = tid & 127;
    const int i   = blockIdx.x * 2 + rr;

    __shared__ float s[2][SEQD];
    if (tid < 2 * SEQD)
        s[tid / SEQD][tid % SEQD] = seq[(blockIdx.x * 2 + tid / SEQD) * SEQD + tid % SEQD];
    __syncthreads();

    float a = bk[c] + bpos[c];
    #pragma unroll
    for (int d = 0; d < SEQD; d++) a += s[rr][d] * Wk[d * ZD + c];
    g_kb[i * ZD + c] = a;
}

// ---------------------------------------------------------------------------
// Fused main kernel: 1920 blocks x 128 threads.
//   b % 5 in {0..3} -> m-path block (1536 total: l x row-half)
//   b % 5 == 4      -> z-path block (384 total: 4 j's x i-half)
// ---------------------------------------------------------------------------
__global__ __launch_bounds__(128, 4) void mainkern(
    const float* __restrict__ seq,  const float* __restrict__ msa,
    const float* __restrict__ Wmsa, const float* __restrict__ bmsa,
    const float* __restrict__ Ws,   const float* __restrict__ bs,
    const float* __restrict__ Wq,   const float* __restrict__ bq,
    const float* __restrict__ Wpos, const float* __restrict__ Wpos2,
    const float* __restrict__ bpos2,
    float* __restrict__ outm, float* __restrict__ outz)
{
    const int b   = blockIdx.x;
    const int tid = threadIdx.x;
    const int sel = b % 5;

    if (sel == 4) {
        // ------------- z-path: z[i,j,:] = sq[j] + kb[i] + Wpos[rel] ---------
        const int zid = b / 5;            // 0..383
        const int j   = (zid >> 1) * 4 + (tid >> 5);
        const int c   = (tid & 31) * 4;

        float4 q;
        q.x = bq[c]; q.y = bq[c + 1]; q.z = bq[c + 2]; q.w = bq[c + 3];
        #pragma unroll
        for (int d = 0; d < SEQD; d++) {
            const float  sv = seq[j * SEQD + d];
            const float4 w  = ld4(Wq + d * ZD + c);
            q.x += sv * w.x; q.y += sv * w.y; q.z += sv * w.z; q.w += sv * w.w;
        }
        const ull q01 = pk2(q.x, q.y);
        const ull q23 = pk2(q.z, q.w);

        const int i0 = (zid & 1) * (LSEQ / 2);
        for (int ib = i0; ib < i0 + LSEQ / 2; ib += 4) {
            ulonglong2 kb0 = *reinterpret_cast<const ulonglong2*>(&g_kb[(ib + 0) * ZD + c]);
            ulonglong2 kb1 = *reinterpret_cast<const ulonglong2*>(&g_kb[(ib + 1) * ZD + c]);
            ulonglong2 kb2 = *reinterpret_cast<const ulonglong2*>(&g_kb[(ib + 2) * ZD + c]);
            ulonglong2 kb3 = *reinterpret_cast<const ulonglong2*>(&g_kb[(ib + 3) * ZD + c]);
            #pragma unroll
            for (int u = 0; u < 4; u++) {
                const int i = ib + u;
                const ulonglong2 kb = (u == 0) ? kb0 : (u == 1) ? kb1 : (u == 2) ? kb2 : kb3;
                int rel = j - i;
                rel = min(max(rel, -RC), RC) + RC;
                const ulonglong2 wp = *reinterpret_cast<const ulonglong2*>(&Wpos[rel * ZD + c]);
                const ull o01 = add2(add2(q01, kb.x), wp.x);
                const ull o23 = add2(add2(q23, kb.y), wp.y);
                st2cs(&outz[((long)i * LSEQ + j) * ZD + c], o01, o23);
            }
        }
        return;
    }

    // ------------ m-path: m[n,l,:] = msa[n,l,:]@Wmsa + sp[l,:] --------------
    const int mid = (b / 5) * 4 + sel;    // 0..1535
    const int l   = mid >> 1;
    const int n0  = (mid & 1) * 128;      // row-half base
    const int rg  = tid >> 6;             // 0..1 (64 rows each)
    const int c   = (tid & 63) * 4;

    __shared__ float rowsT[MSAD * RSTRIDE];   // k-major, each value DUPLICATED
    __shared__ float srow[SEQD];

    if (tid < SEQD) srow[tid] = seq[l * SEQD + tid];
    for (int idx = tid; idx < 128 * MSAD; idx += 128) {
        const int n = idx / MSAD;
        const int k = idx - n * MSAD;
        const float v = msa[((n0 + n) * LSEQ + l) * MSAD + k];
        *reinterpret_cast<float2*>(&rowsT[k * RSTRIDE + 2 * n]) = make_float2(v, v);
    }
    __syncthreads();

    // per-thread weights, channel-packed f32x2 (92 regs)
    ull w0[MSAD], w1[MSAD];
    #pragma unroll
    for (int k = 0; k < MSAD; k++) {
        const float4 w = ld4(Wmsa + k * MD + c);
        w0[k] = pk2(w.x, w.y);
        w1[k] = pk2(w.z, w.w);
    }

    // sp[l, c..c+3]
    float4 sp;
    sp.x = bs[c]     + bpos2[c]     + bmsa[c];
    sp.y = bs[c + 1] + bpos2[c + 1] + bmsa[c + 1];
    sp.z = bs[c + 2] + bpos2[c + 2] + bmsa[c + 2];
    sp.w = bs[c + 3] + bpos2[c + 3] + bmsa[c + 3];
    #pragma unroll
    for (int d = 0; d < SEQD; d++) {
        const float  sv = srow[d];
        const float4 w  = ld4(Ws + d * MD + c);
        sp.x += sv * w.x; sp.y += sv * w.y; sp.z += sv * w.z; sp.w += sv * w.w;
    }
    #pragma unroll
    for (int bb = 0; bb < NB; bb++)
        if ((l >> bb) & 1) {
            const float4 w = ld4(Wpos2 + bb * MD + c);
            sp.x += w.x; sp.y += w.y; sp.z += w.z; sp.w += w.w;
        }
    const ull sp01 = pk2(sp.x, sp.y);
    const ull sp23 = pk2(sp.z, sp.w);

    // main loop: 4 rows / iter, 8 independent FFMA2 chains, zero dup-movs
    for (int t = 0; t < 16; t++) {
        const int r = rg * 64 + t * 4;    // local row base (mult of 4)

        ull a0 = sp01, b0 = sp23;         // row r
        ull a1 = sp01, b1 = sp23;         // row r+1
        ull a2 = sp01, b2 = sp23;         // row r+2
        ull a3 = sp01, b3 = sp23;         // row r+3

        #pragma unroll
        for (int k = 0; k < MSAD; k++) {
            const float* base = &rowsT[k * RSTRIDE + 2 * r];
            const ulonglong2 d01 = *reinterpret_cast<const ulonglong2*>(base);     // {m[r],m[r]},{m[r+1],m[r+1]}
            const ulonglong2 d23 = *reinterpret_cast<const ulonglong2*>(base + 4); // rows r+2, r+3
            a0 = fma2(w0[k], d01.x, a0);  b0 = fma2(w1[k], d01.x, b0);
            a1 = fma2(w0[k], d01.y, a1);  b1 = fma2(w1[k], d01.y, b1);
            a2 = fma2(w0[k], d23.x, a2);  b2 = fma2(w1[k], d23.x, b2);
            a3 = fma2(w0[k], d23.y, a3);  b3 = fma2(w1[k], d23.y, b3);
        }

        float* o = &outm[((long)(n0 + r) * LSEQ + l) * MD + c];
        const long stride = (long)LSEQ * MD;
        st2cs(o,              a0, b0);
        st2cs(o + stride,     a1, b1);
        st2cs(o + 2 * stride, a2, b2);
        st2cs(o + 3 * stride, a3, b3);
    }
}

// ---------------------------------------------------------------------------
extern "C" void kernel_launch(void* const* d_in, const int* in_sizes, int n_in,
                              void* d_out, int out_size)
{
    const float* seq   = (const float*)d_in[0];
    const float* msa   = (const float*)d_in[1];
    const float* Wmsa  = (const float*)d_in[2];
    const float* bmsa  = (const float*)d_in[3];
    const float* Ws    = (const float*)d_in[4];
    const float* bs    = (const float*)d_in[5];
    const float* Wq    = (const float*)d_in[6];
    const float* bq    = (const float*)d_in[7];
    const float* Wk    = (const float*)d_in[8];
    const float* bk    = (const float*)d_in[9];
    const float* Wpos  = (const float*)d_in[10];
    const float* bpos  = (const float*)d_in[11];
    const float* Wpos2 = (const float*)d_in[12];
    const float* bpos2 = (const float*)d_in[13];

    float* outm = (float*)d_out;
    float* outz = outm + (long)NSEQ * LSEQ * MD;

    kbkern<<<LSEQ / 2, 256>>>(seq, Wk, bk, bpos);
    mainkern<<<1920, 128>>>(seq, msa, Wmsa, bmsa, Ws, bs, Wq, bq,
                            Wpos, Wpos2, bpos2, outm, outz);
}

// round 5
// speedup vs baseline: 1.1821x; 1.1821x over previous
#include <cuda_runtime.h>

#define LSEQ 768
#define NSEQ 256
#define MD   256
#define MSAD 23
#define SEQD 22
#define ZD   128
#define NB   14
#define RC   32
#define PSTRIDE 48    // floats per row-pair in smem: 23 k * 2 + pad

// Scratch: kb[i,:] = seq@Wk + bk + bpos  (384 KB)
__device__ float g_kb[LSEQ * ZD];

// ---- packed f32x2 helpers (sm_103a, PTX-only) ----
typedef unsigned long long ull;
__device__ __forceinline__ ull pk2(float a, float b) {
    ull r; asm("mov.b64 %0, {%1, %2};" : "=l"(r) : "f"(a), "f"(b)); return r;
}
__device__ __forceinline__ ull dup2(float a) {
    ull r; asm("mov.b64 %0, {%1, %1};" : "=l"(r) : "f"(a)); return r;
}
__device__ __forceinline__ void upk2(ull v, float& a, float& b) {
    asm("mov.b64 {%0, %1}, %2;" : "=f"(a), "=f"(b) : "l"(v));
}
__device__ __forceinline__ ull fma2(ull a, ull b, ull c) {
    ull d; asm("fma.rn.f32x2 %0, %1, %2, %3;" : "=l"(d) : "l"(a), "l"(b), "l"(c));
    return d;
}
__device__ __forceinline__ float4 ld4(const float* p) {
    return *reinterpret_cast<const float4*>(p);
}

// ---------------------------------------------------------------------------
// kb precompute: 2 rows per 256-thread block.
// ---------------------------------------------------------------------------
__global__ __launch_bounds__(256) void kbkern(
    const float* __restrict__ seq, const float* __restrict__ Wk,
    const float* __restrict__ bk,  const float* __restrict__ bpos)
{
    const int tid = threadIdx.x;
    const int rr  = tid >> 7;
    const int c   = tid & 127;
    const int i   = blockIdx.x * 2 + rr;

    __shared__ float s[2][SEQD];
    if (tid < 2 * SEQD)
        s[tid / SEQD][tid % SEQD] = seq[(blockIdx.x * 2 + tid / SEQD) * SEQD + tid % SEQD];
    __syncthreads();

    float a = bk[c] + bpos[c];
    #pragma unroll
    for (int d = 0; d < SEQD; d++) a += s[rr][d] * Wk[d * ZD + c];
    g_kb[i * ZD + c] = a;
}

// ---------------------------------------------------------------------------
// Fused main kernel: 1152 blocks x 128 threads.
//   blockIdx % 3 in {0,1} -> m-path (one block per l)
//   blockIdx % 3 == 2     -> z-path (4 j's, half the i range)
// ---------------------------------------------------------------------------
__global__ __launch_bounds__(128, 4) void mainkern(
    const float* __restrict__ seq,  const float* __restrict__ msa,
    const float* __restrict__ Wmsa, const float* __restrict__ bmsa,
    const float* __restrict__ Ws,   const float* __restrict__ bs,
    const float* __restrict__ Wq,   const float* __restrict__ bq,
    const float* __restrict__ Wpos, const float* __restrict__ Wpos2,
    const float* __restrict__ bpos2,
    float* __restrict__ outm, float* __restrict__ outz)
{
    const int b   = blockIdx.x;
    const int tid = threadIdx.x;
    const int sel = b % 3;

    if (sel == 2) {
        // ------------- z-path: z[i,j,:] = sq[j] + kb[i] + Wpos[rel] ---------
        const int zid   = b / 3;
        const int jt    = zid >> 1;
        const int ihalf = zid & 1;
        const int j     = jt * 4 + (tid >> 5);
        const int c     = (tid & 31) * 4;

        float4 q;
        q.x = bq[c]; q.y = bq[c + 1]; q.z = bq[c + 2]; q.w = bq[c + 3];
        #pragma unroll
        for (int d = 0; d < SEQD; d++) {
            const float  sv = seq[j * SEQD + d];
            const float4 w  = ld4(Wq + d * ZD + c);
            q.x += sv * w.x; q.y += sv * w.y; q.z += sv * w.z; q.w += sv * w.w;
        }

        const int i0 = ihalf * (LSEQ / 2);
        for (int ib = i0; ib < i0 + LSEQ / 2; ib += 8) {
            // batch 8 independent kb loads (MLP=8 over L2 latency)
            float4 kbv[8];
            #pragma unroll
            for (int u = 0; u < 8; u++)
                kbv[u] = __ldg(reinterpret_cast<const float4*>(&g_kb[(ib + u) * ZD + c]));
            #pragma unroll
            for (int u = 0; u < 8; u++) {
                const int i = ib + u;
                int rel = j - i;
                rel = min(max(rel, -RC), RC) + RC;
                const float4 wp = ld4(Wpos + rel * ZD + c);
                float4 o;
                o.x = q.x + kbv[u].x + wp.x;
                o.y = q.y + kbv[u].y + wp.y;
                o.z = q.z + kbv[u].z + wp.z;
                o.w = q.w + kbv[u].w + wp.w;
                __stcs(reinterpret_cast<float4*>(&outz[((long)i * LSEQ + j) * ZD + c]), o);
            }
        }
        return;
    }

    // ------------ m-path: m[n,l,:] = msa[n,l,:]@Wmsa + sp[l,:] --------------
    const int l  = (b / 3) * 2 + sel;
    const int rg = tid >> 6;              // 0..1
    const int c  = (tid & 63) * 4;

    // Row-PAIR interleaved layout: pairs[p][k][s] = msa[2p+s, l, k]
    // One LDS.64 at (p*PSTRIDE + 2k) yields both rows' k-values.
    __shared__ float pairs[(NSEQ / 2) * PSTRIDE];   // 24.6 KB
    __shared__ float srow[SEQD];

    if (tid < SEQD) srow[tid] = seq[l * SEQD + tid];
    for (int idx = tid; idx < NSEQ * MSAD; idx += 128) {
        const int n = idx / MSAD;
        const int k = idx - n * MSAD;
        const float v = msa[(n * LSEQ + l) * MSAD + k];
        pairs[(n >> 1) * PSTRIDE + 2 * k + (n & 1)] = v;
    }
    __syncthreads();

    // per-thread weights, channel-packed f32x2 (92 regs)
    ull w0[MSAD], w1[MSAD];
    #pragma unroll
    for (int k = 0; k < MSAD; k++) {
        const float4 w = ld4(Wmsa + k * MD + c);
        w0[k] = pk2(w.x, w.y);
        w1[k] = pk2(w.z, w.w);
    }

    // sp[l, c..c+3]
    float4 sp;
    sp.x = bs[c]     + bpos2[c]     + bmsa[c];
    sp.y = bs[c + 1] + bpos2[c + 1] + bmsa[c + 1];
    sp.z = bs[c + 2] + bpos2[c + 2] + bmsa[c + 2];
    sp.w = bs[c + 3] + bpos2[c + 3] + bmsa[c + 3];
    #pragma unroll
    for (int d = 0; d < SEQD; d++) {
        const float  sv = srow[d];
        const float4 w  = ld4(Ws + d * MD + c);
        sp.x += sv * w.x; sp.y += sv * w.y; sp.z += sv * w.z; sp.w += sv * w.w;
    }
    #pragma unroll
    for (int bb = 0; bb < NB; bb++)
        if ((l >> bb) & 1) {
            const float4 w = ld4(Wpos2 + bb * MD + c);
            sp.x += w.x; sp.y += w.y; sp.z += w.z; sp.w += w.w;
        }
    const ull sp01 = pk2(sp.x, sp.y);
    const ull sp23 = pk2(sp.z, sp.w);

    // main loop: one row-PAIR per iteration -> 4 independent fma2 chains,
    // 23 LDS.64 per pair (halved LSU pressure vs scalar LDS).
    for (int it = 0; it < NSEQ / 4; it++) {
        const int p  = it * 2 + rg;       // pair index 0..127
        const int na = p * 2;             // rows na, na+1
        const float* base = &pairs[p * PSTRIDE];

        ull a01 = sp01, a23 = sp23;       // row na
        ull b01 = sp01, b23 = sp23;       // row na+1
        #pragma unroll
        for (int k = 0; k < MSAD; k++) {
            const float2 v = *reinterpret_cast<const float2*>(base + 2 * k);  // LDS.64
            const ull pa = dup2(v.x);
            const ull pb = dup2(v.y);
            a01 = fma2(w0[k], pa, a01);
            a23 = fma2(w1[k], pa, a23);
            b01 = fma2(w0[k], pb, b01);
            b23 = fma2(w1[k], pb, b23);
        }
        float4 oa, ob;
        upk2(a01, oa.x, oa.y); upk2(a23, oa.z, oa.w);
        upk2(b01, ob.x, ob.y); upk2(b23, ob.z, ob.w);
        __stcs(reinterpret_cast<float4*>(&outm[((long)na * LSEQ + l) * MD + c]), oa);
        __stcs(reinterpret_cast<float4*>(&outm[((long)(na + 1) * LSEQ + l) * MD + c]), ob);
    }
}

// ---------------------------------------------------------------------------
extern "C" void kernel_launch(void* const* d_in, const int* in_sizes, int n_in,
                              void* d_out, int out_size)
{
    const float* seq   = (const float*)d_in[0];
    const float* msa   = (const float*)d_in[1];
    const float* Wmsa  = (const float*)d_in[2];
    const float* bmsa  = (const float*)d_in[3];
    const float* Ws    = (const float*)d_in[4];
    const float* bs    = (const float*)d_in[5];
    const float* Wq    = (const float*)d_in[6];
    const float* bq    = (const float*)d_in[7];
    const float* Wk    = (const float*)d_in[8];
    const float* bk    = (const float*)d_in[9];
    const float* Wpos  = (const float*)d_in[10];
    const float* bpos  = (const float*)d_in[11];
    const float* Wpos2 = (const float*)d_in[12];
    const float* bpos2 = (const float*)d_in[13];

    float* outm = (float*)d_out;
    float* outz = outm + (long)NSEQ * LSEQ * MD;

    kbkern<<<LSEQ / 2, 256>>>(seq, Wk, bk, bpos);
    mainkern<<<1152, 128>>>(seq, msa, Wmsa, bmsa, Ws, bs, Wq, bq,
                            Wpos, Wpos2, bpos2, outm, outz);
}